// round 1
// baseline (speedup 1.0000x reference)
#include <cuda_runtime.h>
#include <math.h>

// Problem constants
#define BB 128
#define HH 16
#define WW 48
#define DD 512
#define UU 512
#define HW (HH*WW)          // 768
#define MM (BB*HW)          // 98304

// Scratch (device globals — no allocation allowed)
__device__ float g_dec_proj[BB*UU];   // dec @ W2 + b1 + b2
__device__ float g_scores[MM];        // pre-softmax scores

// ---------------------------------------------------------------------------
// K1: dec_proj[b,u] = sum_d dec[b,d]*W2[d,u] + W1_b[u] + W2_b[u]
// grid(128), block(512)
// ---------------------------------------------------------------------------
__global__ void dec_proj_kernel(const float* __restrict__ dec,
                                const float* __restrict__ W2,
                                const float* __restrict__ b1,
                                const float* __restrict__ b2) {
    __shared__ float s_dec[DD];
    int b = blockIdx.x;
    int t = threadIdx.x;                 // 0..511 == u
    s_dec[t] = dec[b*DD + t];
    __syncthreads();
    float acc = b1[t] + b2[t];
    #pragma unroll 8
    for (int d = 0; d < DD; d++)
        acc += s_dec[d] * W2[(size_t)d*UU + t];
    g_dec_proj[b*UU + t] = acc;
}

// ---------------------------------------------------------------------------
// K2: scores. For 64 rows of the flattened (b,h,w) axis:
//   c = enc_rows @ W1  (tiled 64x64, K=512)
//   h = tanh(c + dec_proj[b,:])
//   score = h . V_w  (+ V_b)
// 256 threads, 4x4 microtile. grid(1536).
// 768 % 64 == 0, so a 64-row tile never crosses a batch boundary.
// ---------------------------------------------------------------------------
#define TM 64
#define TN 64
#define TK 16

__global__ __launch_bounds__(256) void score_kernel(
    const float* __restrict__ enc, const float* __restrict__ W1,
    const float* __restrict__ Vw, const float* __restrict__ Vb) {

    __shared__ float As[TK][68];    // transposed A tile, padded (68*4B % 16 == 0)
    __shared__ float Bs[TK][TN];
    __shared__ float red[TM][17];

    const int tid = threadIdx.x;
    const int tx = tid & 15;        // n direction
    const int ty = tid >> 4;        // m direction
    const int row0 = blockIdx.x * TM;
    const int b = row0 / HW;
    const float* __restrict__ dprow = g_dec_proj + b*UU;

    float sacc0 = 0.f, sacc1 = 0.f, sacc2 = 0.f, sacc3 = 0.f;

    for (int nt = 0; nt < UU; nt += TN) {
        float c[4][4];
        #pragma unroll
        for (int i = 0; i < 4; i++)
            #pragma unroll
            for (int j = 0; j < 4; j++) c[i][j] = 0.f;

        for (int kt = 0; kt < DD; kt += TK) {
            // load A tile (64 rows x 16 k), store transposed
            {
                int r  = tid >> 2;            // 0..63
                int kc = (tid & 3) * 4;       // 0,4,8,12
                float4 v = *(const float4*)(enc + (size_t)(row0 + r)*DD + kt + kc);
                As[kc+0][r] = v.x; As[kc+1][r] = v.y;
                As[kc+2][r] = v.z; As[kc+3][r] = v.w;
            }
            // load B tile (16 k x 64 n)
            {
                int k  = tid >> 4;            // 0..15
                int nc = (tid & 15) * 4;
                *(float4*)(&Bs[k][nc]) =
                    *(const float4*)(W1 + (size_t)(kt + k)*UU + nt + nc);
            }
            __syncthreads();
            #pragma unroll
            for (int kk = 0; kk < TK; kk++) {
                float4 a  = *(const float4*)(&As[kk][ty*4]);
                float4 bb = *(const float4*)(&Bs[kk][tx*4]);
                c[0][0] += a.x*bb.x; c[0][1] += a.x*bb.y; c[0][2] += a.x*bb.z; c[0][3] += a.x*bb.w;
                c[1][0] += a.y*bb.x; c[1][1] += a.y*bb.y; c[1][2] += a.y*bb.z; c[1][3] += a.y*bb.w;
                c[2][0] += a.z*bb.x; c[2][1] += a.z*bb.y; c[2][2] += a.z*bb.z; c[2][3] += a.z*bb.w;
                c[3][0] += a.w*bb.x; c[3][1] += a.w*bb.y; c[3][2] += a.w*bb.z; c[3][3] += a.w*bb.w;
            }
            __syncthreads();
        }

        // epilogue: add dec_proj, tanh, dot with V
        #pragma unroll
        for (int j = 0; j < 4; j++) {
            int u = nt + tx*4 + j;
            float dp = dprow[u];
            float vw = Vw[u];
            sacc0 += tanhf(c[0][j] + dp) * vw;
            sacc1 += tanhf(c[1][j] + dp) * vw;
            sacc2 += tanhf(c[2][j] + dp) * vw;
            sacc3 += tanhf(c[3][j] + dp) * vw;
        }
    }

    // reduce partial scores across the 16 tx lanes per row
    red[ty*4+0][tx] = sacc0;
    red[ty*4+1][tx] = sacc1;
    red[ty*4+2][tx] = sacc2;
    red[ty*4+3][tx] = sacc3;
    __syncthreads();
    if (tid < TM) {
        float s = 0.f;
        #pragma unroll
        for (int j = 0; j < 16; j++) s += red[tid][j];
        g_scores[row0 + tid] = s + Vb[0];
    }
}

// ---------------------------------------------------------------------------
// K3: softmax over H (axis=1) for each (b,w). Writes attention weights.
// ---------------------------------------------------------------------------
__global__ void softmax_kernel(float* __restrict__ attn) {
    int idx = blockIdx.x * blockDim.x + threadIdx.x;   // 0..B*W-1
    if (idx >= BB*WW) return;
    int b = idx / WW, w = idx - b*WW;
    const float* s = g_scores + b*HW + w;
    float mx = -1e30f;
    #pragma unroll
    for (int h = 0; h < HH; h++) mx = fmaxf(mx, s[h*WW]);
    float e[HH];
    float sum = 0.f;
    #pragma unroll
    for (int h = 0; h < HH; h++) { e[h] = __expf(s[h*WW] - mx); sum += e[h]; }
    float inv = 1.0f / sum;
    #pragma unroll
    for (int h = 0; h < HH; h++)
        attn[b*HW + h*WW + w] = e[h] * inv;
}

// ---------------------------------------------------------------------------
// K4: context[b,d] = sum_{hw} attn[b,hw] * enc[b,hw,d]
// grid(128), block(512): thread t owns column d=t.
// ---------------------------------------------------------------------------
__global__ void context_kernel(const float* __restrict__ enc,
                               const float* __restrict__ attn,
                               float* __restrict__ ctx) {
    __shared__ float s_a[HW];
    int b = blockIdx.x;
    int t = threadIdx.x;   // 0..511
    for (int i = t; i < HW; i += 512) s_a[i] = attn[b*HW + i];
    __syncthreads();
    const float* __restrict__ e = enc + (size_t)b*HW*DD + t;
    float acc = 0.f;
    #pragma unroll 8
    for (int i = 0; i < HW; i++)
        acc += s_a[i] * e[(size_t)i*DD];
    ctx[b*DD + t] = acc;
}

// ---------------------------------------------------------------------------
extern "C" void kernel_launch(void* const* d_in, const int* in_sizes, int n_in,
                              void* d_out, int out_size) {
    const float* dec  = (const float*)d_in[0];   // (128, 512)
    const float* enc  = (const float*)d_in[1];   // (128, 16, 48, 512)
    const float* W1w  = (const float*)d_in[2];   // (512, 512)
    const float* W1b  = (const float*)d_in[3];   // (512,)
    const float* W2w  = (const float*)d_in[4];   // (512, 512)
    const float* W2b  = (const float*)d_in[5];   // (512,)
    const float* Vw   = (const float*)d_in[6];   // (512, 1)
    const float* Vb   = (const float*)d_in[7];   // (1,)

    float* ctx_out  = (float*)d_out;             // (128, 512)  = 65536 floats
    float* attn_out = (float*)d_out + BB*DD;     // (128,16,48,1) = 98304 floats

    dec_proj_kernel<<<BB, DD>>>(dec, W2w, W1b, W2b);
    score_kernel<<<MM/TM, 256>>>(enc, W1w, Vw, Vb);
    softmax_kernel<<<(BB*WW + 127)/128, 128>>>(attn_out);
    context_kernel<<<BB, DD>>>(enc, attn_out, ctx_out);
}

// round 3
// speedup vs baseline: 2.2345x; 2.2345x over previous
#include <cuda_runtime.h>
#include <cuda_bf16.h>
#include <cstdint>
#include <math.h>

// Problem constants
#define BB 128
#define HH 16
#define WW 48
#define DD 512
#define UU 512
#define HW (HH*WW)          // 768
#define MM (BB*HW)          // 98304

// ---------------------------------------------------------------------------
// Device globals (scratch; no allocation allowed)
// ---------------------------------------------------------------------------
__device__ float         g_dec_proj[BB*UU];       // dec @ W2 + b1 + b2
__device__ float         g_part[2*MM];            // partial scores per N-half
__device__ __nv_bfloat16 g_W1T_hi[UU*DD];         // W1^T split-hi [u][k]
__device__ __nv_bfloat16 g_W1T_lo[UU*DD];         // W1^T split-lo [u][k]
__device__ __nv_bfloat16 g_enc_hi[(size_t)MM*DD]; // enc split-hi  [m][k]
__device__ __nv_bfloat16 g_enc_lo[(size_t)MM*DD]; // enc split-lo  [m][k]

// ---------------------------------------------------------------------------
// Helpers
// ---------------------------------------------------------------------------
__device__ __forceinline__ uint32_t smem_u32(const void* p) {
    uint32_t a;
    asm("{ .reg .u64 t; cvta.to.shared.u64 t, %1; cvt.u32.u64 %0, t; }"
        : "=r"(a) : "l"(p));
    return a;
}

__device__ __forceinline__ void cp16(uint32_t s, const void* g) {
    asm volatile("cp.async.cg.shared.global [%0], [%1], 16;"
                 :: "r"(s), "l"(g) : "memory");
}
__device__ __forceinline__ void cp_commit() {
    asm volatile("cp.async.commit_group;" ::: "memory");
}

__device__ __forceinline__ void mma_bf16(float* c, const uint32_t* a,
                                         uint32_t b0, uint32_t b1) {
    asm volatile("mma.sync.aligned.m16n8k16.row.col.f32.bf16.bf16.f32 "
                 "{%0,%1,%2,%3}, {%4,%5,%6,%7}, {%8,%9}, {%0,%1,%2,%3};"
                 : "+f"(c[0]), "+f"(c[1]), "+f"(c[2]), "+f"(c[3])
                 : "r"(a[0]), "r"(a[1]), "r"(a[2]), "r"(a[3]),
                   "r"(b0), "r"(b1));
}

// ---------------------------------------------------------------------------
// K0a: W1 -> transposed bf16 hi/lo splits  (g_W1T_*[u][k] = split(W1[k][u]))
// ---------------------------------------------------------------------------
__global__ void prep_w1_kernel(const float* __restrict__ W1) {
    int idx = blockIdx.x * 256 + threadIdx.x;    // 0..262143
    int k = idx >> 9, u = idx & 511;
    float x = W1[idx];
    __nv_bfloat16 h = __float2bfloat16(x);
    g_W1T_hi[u*DD + k] = h;
    g_W1T_lo[u*DD + k] = __float2bfloat16(x - __bfloat162float(h));
}

// ---------------------------------------------------------------------------
// K0b: enc fp32 -> bf16 hi/lo splits (4 elems/thread)
// ---------------------------------------------------------------------------
__global__ __launch_bounds__(256) void prep_enc_kernel(const float* __restrict__ enc) {
    size_t i4 = (size_t)blockIdx.x * 256 + threadIdx.x;  // float4 index
    float4 v = ((const float4*)enc)[i4];
    __nv_bfloat162 h01 = __floats2bfloat162_rn(v.x, v.y);
    __nv_bfloat162 h23 = __floats2bfloat162_rn(v.z, v.w);
    __nv_bfloat162 l01 = __floats2bfloat162_rn(v.x - __low2float(h01),
                                               v.y - __high2float(h01));
    __nv_bfloat162 l23 = __floats2bfloat162_rn(v.z - __low2float(h23),
                                               v.w - __high2float(h23));
    ((uint2*)g_enc_hi)[i4] = make_uint2(reinterpret_cast<uint32_t&>(h01),
                                        reinterpret_cast<uint32_t&>(h23));
    ((uint2*)g_enc_lo)[i4] = make_uint2(reinterpret_cast<uint32_t&>(l01),
                                        reinterpret_cast<uint32_t&>(l23));
}

// ---------------------------------------------------------------------------
// K1: dec_proj[b,u] = sum_d dec[b,d]*W2[d,u] + W1_b[u] + W2_b[u]
// ---------------------------------------------------------------------------
__global__ void dec_proj_kernel(const float* __restrict__ dec,
                                const float* __restrict__ W2,
                                const float* __restrict__ b1,
                                const float* __restrict__ b2) {
    __shared__ float s_dec[DD];
    int b = blockIdx.x;
    int t = threadIdx.x;
    s_dec[t] = dec[b*DD + t];
    __syncthreads();
    float acc = b1[t] + b2[t];
    #pragma unroll 8
    for (int d = 0; d < DD; d++)
        acc += s_dec[d] * W2[(size_t)d*UU + t];
    g_dec_proj[b*UU + t] = acc;
}

// ---------------------------------------------------------------------------
// K2: split-bf16 score GEMM on mma.sync + fused tanh/V epilogue.
//   Logical GEMM: C[M=98304, U=512] over K'=1536:
//     A' = [enc_hi | enc_hi | enc_lo],  B' = [W1T_hi | W1T_lo | W1T_hi]
//   CTA: tile 128 (m) x 256 (n), 512 threads, K-chunk 64, 2-stage cp.async.
//   grid.x = 1536: mtile = bx>>1, nt = bx&1 (n-fast for A reuse in L2).
// ---------------------------------------------------------------------------
#define Bb16 2
#define STAGE 49152          // A 128x64x2 (16K) + B 256x64x2 (32K)
#define SMEM_DYN (2*STAGE)   // 96KB

__global__ __launch_bounds__(512, 1) void score_kernel(const float* __restrict__ Vw) {
    extern __shared__ char dsm[];
    __shared__ float dp_s[256];
    __shared__ float vw_s[256];
    __shared__ float s_red[4][128];

    const uint32_t sb = smem_u32(dsm);
    const int tid  = threadIdx.x;
    const int wid  = tid >> 5;
    const int lane = tid & 31;
    const int mtile = blockIdx.x >> 1;
    const int nt    = blockIdx.x & 1;
    const int row0  = mtile * 128;
    const int b     = mtile / 6;          // 768/128 = 6 tiles per batch
    const int m0 = (wid >> 2) * 32;       // warp m-offset (0..96)
    const int n0 = (wid & 3) * 64;        // warp n-offset (0..192)
    const int rl = lane >> 2;             // 0..7
    const int qt = lane & 3;              // 0..3

    // Preload epilogue vectors (this CTA's 256-u slice)
    if (tid < 256) {
        dp_s[tid] = g_dec_proj[b*UU + nt*256 + tid];
        vw_s[tid] = Vw[nt*256 + tid];
    }

    float acc[2][8][4];
    #pragma unroll
    for (int mi = 0; mi < 2; mi++)
        #pragma unroll
        for (int j = 0; j < 8; j++)
            #pragma unroll
            for (int c = 0; c < 4; c++) acc[mi][j][c] = 0.f;

    // ---- async-load one K'=64 chunk into stage (c&1) ----
    auto issue = [&](int c) {
        const int term = c >> 3;                 // 0,1,2
        const int kk = (c & 7) * 64;
        const __nv_bfloat16* Asrc = (term < 2) ? g_enc_hi : g_enc_lo;
        const __nv_bfloat16* Bsrc = (term == 1) ? g_W1T_lo : g_W1T_hi;
        const uint32_t stg = sb + (uint32_t)(c & 1) * STAGE;
        #pragma unroll
        for (int i = 0; i < 2; i++) {            // A: 1024 x 16B
            int id = tid + i*512;
            int r = id >> 3, j = id & 7;
            cp16(stg + r*128 + ((j ^ (r & 7)) << 4),
                 Asrc + (size_t)(row0 + r)*DD + kk + j*8);
        }
        #pragma unroll
        for (int i = 0; i < 4; i++) {            // B: 2048 x 16B
            int id = tid + i*512;
            int r = id >> 3, j = id & 7;
            cp16(stg + 16384 + r*128 + ((j ^ (r & 7)) << 4),
                 Bsrc + (size_t)(nt*256 + r)*DD + kk + j*8);
        }
        cp_commit();
    };

    issue(0);
    for (int c = 0; c < 24; c++) {
        if (c + 1 < 24) {
            issue(c + 1);
            asm volatile("cp.async.wait_group 1;" ::: "memory");
        } else {
            asm volatile("cp.async.wait_group 0;" ::: "memory");
        }
        __syncthreads();

        const char* sA = dsm + (c & 1) * STAGE;
        const char* sB = sA + 16384;
        #pragma unroll
        for (int ks = 0; ks < 4; ks++) {
            const uint32_t kb  = (uint32_t)(ks*32 + qt*4);
            const uint32_t swk = (uint32_t)(rl << 4);
            uint32_t a[2][4];
            #pragma unroll
            for (int mi = 0; mi < 2; mi++) {
                const char* base = sA + (size_t)(m0 + mi*16 + rl) * 128;
                a[mi][0] = *(const uint32_t*)(base + (kb ^ swk));
                a[mi][1] = *(const uint32_t*)(base + 8*128 + (kb ^ swk));
                a[mi][2] = *(const uint32_t*)(base + ((kb + 16) ^ swk));
                a[mi][3] = *(const uint32_t*)(base + 8*128 + ((kb + 16) ^ swk));
            }
            #pragma unroll
            for (int j = 0; j < 8; j++) {
                const char* bbase = sB + (size_t)(n0 + j*8 + rl) * 128;
                uint32_t b0 = *(const uint32_t*)(bbase + (kb ^ swk));
                uint32_t b1 = *(const uint32_t*)(bbase + ((kb + 16) ^ swk));
                mma_bf16(acc[0][j], a[0], b0, b1);
                mma_bf16(acc[1][j], a[1], b0, b1);
            }
        }
        __syncthreads();
    }

    // ---- epilogue: tanh + V-dot ----
    float p[4] = {0.f, 0.f, 0.f, 0.f};
    #pragma unroll
    for (int mi = 0; mi < 2; mi++)
        #pragma unroll
        for (int j = 0; j < 8; j++)
            #pragma unroll
            for (int cc = 0; cc < 4; cc++) {
                int u = n0 + j*8 + qt*2 + (cc & 1);
                int h = cc >> 1;
                p[mi*2 + h] += tanhf(acc[mi][j][cc] + dp_s[u]) * vw_s[u];
            }
    #pragma unroll
    for (int i = 0; i < 4; i++) {
        p[i] += __shfl_xor_sync(0xFFFFFFFF, p[i], 1);
        p[i] += __shfl_xor_sync(0xFFFFFFFF, p[i], 2);
    }
    if (qt == 0) {
        #pragma unroll
        for (int mi = 0; mi < 2; mi++)
            #pragma unroll
            for (int h = 0; h < 2; h++)
                s_red[wid & 3][m0 + mi*16 + h*8 + rl] = p[mi*2 + h];
    }
    __syncthreads();
    if (tid < 128)
        g_part[nt*MM + row0 + tid] =
            (s_red[0][tid] + s_red[1][tid]) + (s_red[2][tid] + s_red[3][tid]);
}

// ---------------------------------------------------------------------------
// K3: softmax over H (axis=1) per (b,w). V_b omitted (shift-invariant).
// ---------------------------------------------------------------------------
__global__ void softmax_kernel(float* __restrict__ attn) {
    int idx = blockIdx.x * blockDim.x + threadIdx.x;
    if (idx >= BB*WW) return;
    int b = idx / WW, w = idx - b*WW;
    const float* p0 = g_part + b*HW + w;
    const float* p1 = g_part + MM + b*HW + w;
    float sc[HH];
    float mx = -1e30f;
    #pragma unroll
    for (int h = 0; h < HH; h++) {
        sc[h] = p0[h*WW] + p1[h*WW];
        mx = fmaxf(mx, sc[h]);
    }
    float sum = 0.f;
    #pragma unroll
    for (int h = 0; h < HH; h++) { sc[h] = __expf(sc[h] - mx); sum += sc[h]; }
    float inv = 1.0f / sum;
    #pragma unroll
    for (int h = 0; h < HH; h++)
        attn[b*HW + h*WW + w] = sc[h] * inv;
}

// ---------------------------------------------------------------------------
// K4: context[b,d] = sum_{hw} attn[b,hw] * enc[b,hw,d]
// ---------------------------------------------------------------------------
__global__ __launch_bounds__(128) void context_kernel(const float* __restrict__ enc,
                                                      const float* __restrict__ attn,
                                                      float* __restrict__ ctx) {
    __shared__ float s_a[HW];
    int b = blockIdx.x;
    int t = threadIdx.x;                       // owns d = 4t..4t+3
    for (int i = t; i < HW; i += 128) s_a[i] = attn[b*HW + i];
    __syncthreads();
    const float4* __restrict__ e = (const float4*)(enc + (size_t)b*HW*DD) + t;
    float4 a0 = {0,0,0,0}, a1 = a0, a2 = a0, a3 = a0;
    #pragma unroll 4
    for (int i = 0; i < HW; i += 4) {
        float w0 = s_a[i], w1 = s_a[i+1], w2 = s_a[i+2], w3 = s_a[i+3];
        float4 e0 = e[(size_t)(i+0)*128];
        float4 e1 = e[(size_t)(i+1)*128];
        float4 e2 = e[(size_t)(i+2)*128];
        float4 e3 = e[(size_t)(i+3)*128];
        a0.x += w0*e0.x; a0.y += w0*e0.y; a0.z += w0*e0.z; a0.w += w0*e0.w;
        a1.x += w1*e1.x; a1.y += w1*e1.y; a1.z += w1*e1.z; a1.w += w1*e1.w;
        a2.x += w2*e2.x; a2.y += w2*e2.y; a2.z += w2*e2.z; a2.w += w2*e2.w;
        a3.x += w3*e3.x; a3.y += w3*e3.y; a3.z += w3*e3.z; a3.w += w3*e3.w;
    }
    float4 r;
    r.x = (a0.x + a1.x) + (a2.x + a3.x);
    r.y = (a0.y + a1.y) + (a2.y + a3.y);
    r.z = (a0.z + a1.z) + (a2.z + a3.z);
    r.w = (a0.w + a1.w) + (a2.w + a3.w);
    ((float4*)(ctx + (size_t)b*DD))[t] = r;
}

// ---------------------------------------------------------------------------
extern "C" void kernel_launch(void* const* d_in, const int* in_sizes, int n_in,
                              void* d_out, int out_size) {
    const float* dec  = (const float*)d_in[0];   // (128, 512)
    const float* enc  = (const float*)d_in[1];   // (128, 16, 48, 512)
    const float* W1w  = (const float*)d_in[2];   // (512, 512)
    const float* W1b  = (const float*)d_in[3];
    const float* W2w  = (const float*)d_in[4];
    const float* W2b  = (const float*)d_in[5];
    const float* Vw   = (const float*)d_in[6];   // (512, 1)
    // V_b unused: cancels in softmax.

    float* ctx_out  = (float*)d_out;             // (128, 512)
    float* attn_out = (float*)d_out + BB*DD;     // (128, 16, 48, 1)

    static bool attr_set = false;
    if (!attr_set) {
        cudaFuncSetAttribute(score_kernel,
                             cudaFuncAttributeMaxDynamicSharedMemorySize, SMEM_DYN);
        attr_set = true;
    }

    prep_w1_kernel<<<1024, 256>>>(W1w);
    prep_enc_kernel<<<(int)((size_t)MM*DD/4/256), 256>>>(enc);
    dec_proj_kernel<<<BB, DD>>>(dec, W2w, W1b, W2b);
    score_kernel<<<(MM/128)*2, 512, SMEM_DYN>>>(Vw);
    softmax_kernel<<<(BB*WW + 127)/128, 128>>>(attn_out);
    context_kernel<<<BB, 128>>>(enc, attn_out, ctx_out);
}